// round 2
// baseline (speedup 1.0000x reference)
#include <cuda_runtime.h>
#include <cuda_bf16.h>

// Problem constants
#define B_DIM 8
#define N_DIM 1024
#define C_DIM 1024
#define H_DIM 16
#define HD    64

// Scratch (static __device__ arrays: allocation-free per harness rules)
__device__ float g_qkv[(size_t)B_DIM * N_DIM * 3 * C_DIM];        // 96 MiB
__device__ float g_ctx[(size_t)B_DIM * N_DIM * C_DIM];            // 32 MiB
__device__ float g_attn[(size_t)B_DIM * H_DIM * N_DIM * N_DIM];   // 512 MiB (fallback if attn not in d_out)

// ---------------------------------------------------------------------------
// Generic tiled SGEMM: C = alpha * A @ op(B) (+ bias), batched via blockIdx.z
// A row-major [M,K] (lda), B row-major; TRANSB=false: B is [K,N] (ldb),
// TRANSB=true: B is [N,K] (ldb) and we compute A @ B^T.
// Batch offset = (z / innerCount) * s?o + (z % innerCount) * s?i.
// All dims assumed multiples of tile sizes (true for this problem).
// ---------------------------------------------------------------------------
template <int BM, int BN, int BK, int TM, int TN, bool TRANSB>
__global__ void __launch_bounds__((BM / TM) * (BN / TN))
sgemm_k(const float* __restrict__ A, const float* __restrict__ B,
        float* __restrict__ C, const float* __restrict__ bias,
        int K, int lda, int ldb, int ldc,
        long sAi, long sAo, long sBi, long sBo, long sCi, long sCo,
        int innerCount, float alpha)
{
    constexpr int THREADS = (BM / TM) * (BN / TN);
    __shared__ float As[BK][BM];
    __shared__ float Bs[BK][BN];

    const int z  = blockIdx.z;
    const int zo = z / innerCount;
    const int zi = z % innerCount;
    A += (long)zo * sAo + (long)zi * sAi;
    B += (long)zo * sBo + (long)zi * sBi;
    C += (long)zo * sCo + (long)zi * sCi;

    const int m0  = blockIdx.y * BM;
    const int n0  = blockIdx.x * BN;
    const int tid = threadIdx.x;
    const int tx  = tid % (BN / TN);
    const int ty  = tid / (BN / TN);

    float acc[TM][TN];
#pragma unroll
    for (int i = 0; i < TM; i++)
#pragma unroll
        for (int j = 0; j < TN; j++) acc[i][j] = 0.0f;

    for (int k0 = 0; k0 < K; k0 += BK) {
        // ---- load A tile [BM x BK] as float4 along K, store transposed ----
        constexpr int A_F4 = BM * BK / 4;
#pragma unroll
        for (int it = 0; it < A_F4 / THREADS; it++) {
            int i   = tid + it * THREADS;
            int row = i / (BK / 4);
            int c4  = i % (BK / 4);
            float4 v = *reinterpret_cast<const float4*>(
                &A[(long)(m0 + row) * lda + k0 + c4 * 4]);
            As[c4 * 4 + 0][row] = v.x;
            As[c4 * 4 + 1][row] = v.y;
            As[c4 * 4 + 2][row] = v.z;
            As[c4 * 4 + 3][row] = v.w;
        }
        // ---- load B tile [BK x BN] ----
        constexpr int B_F4 = BK * BN / 4;
        if (!TRANSB) {
#pragma unroll
            for (int it = 0; it < B_F4 / THREADS; it++) {
                int i   = tid + it * THREADS;
                int row = i / (BN / 4);
                int c4  = i % (BN / 4);
                float4 v = *reinterpret_cast<const float4*>(
                    &B[(long)(k0 + row) * ldb + n0 + c4 * 4]);
                *reinterpret_cast<float4*>(&Bs[row][c4 * 4]) = v;
            }
        } else {
#pragma unroll
            for (int it = 0; it < B_F4 / THREADS; it++) {
                int i  = tid + it * THREADS;
                int n  = i / (BK / 4);
                int k4 = i % (BK / 4);
                float4 v = *reinterpret_cast<const float4*>(
                    &B[(long)(n0 + n) * ldb + k0 + k4 * 4]);
                Bs[k4 * 4 + 0][n] = v.x;
                Bs[k4 * 4 + 1][n] = v.y;
                Bs[k4 * 4 + 2][n] = v.z;
                Bs[k4 * 4 + 3][n] = v.w;
            }
        }
        __syncthreads();

        // ---- compute ----
#pragma unroll
        for (int kk = 0; kk < BK; kk++) {
            float ra[TM], rb[TN];
#pragma unroll
            for (int i = 0; i < TM; i += 4) {
                float4 t = *reinterpret_cast<const float4*>(&As[kk][ty * TM + i]);
                ra[i] = t.x; ra[i + 1] = t.y; ra[i + 2] = t.z; ra[i + 3] = t.w;
            }
#pragma unroll
            for (int j = 0; j < TN; j += 4) {
                float4 t = *reinterpret_cast<const float4*>(&Bs[kk][tx * TN + j]);
                rb[j] = t.x; rb[j + 1] = t.y; rb[j + 2] = t.z; rb[j + 3] = t.w;
            }
#pragma unroll
            for (int i = 0; i < TM; i++)
#pragma unroll
                for (int j = 0; j < TN; j++)
                    acc[i][j] = fmaf(ra[i], rb[j], acc[i][j]);
        }
        __syncthreads();
    }

    // ---- epilogue ----
#pragma unroll
    for (int i = 0; i < TM; i++) {
#pragma unroll
        for (int j = 0; j < TN; j += 4) {
            float4 v;
            v.x = alpha * acc[i][j + 0];
            v.y = alpha * acc[i][j + 1];
            v.z = alpha * acc[i][j + 2];
            v.w = alpha * acc[i][j + 3];
            if (bias != nullptr) {
                int nb = n0 + tx * TN + j;
                v.x += bias[nb + 0];
                v.y += bias[nb + 1];
                v.z += bias[nb + 2];
                v.w += bias[nb + 3];
            }
            *reinterpret_cast<float4*>(
                &C[(long)(m0 + ty * TM + i) * ldc + n0 + tx * TN + j]) = v;
        }
    }
}

// ---------------------------------------------------------------------------
// Row softmax over rows of exactly 1024 floats. One 256-thread block per row;
// each thread owns one float4 in registers (single read, single write).
// ---------------------------------------------------------------------------
__global__ void softmax1024(float* __restrict__ data)
{
    const long row = blockIdx.x;
    float4* p = reinterpret_cast<float4*>(data + row * 1024);
    const int t    = threadIdx.x;
    const int warp = t >> 5;
    const int lane = t & 31;

    float4 v = p[t];
    float m = fmaxf(fmaxf(v.x, v.y), fmaxf(v.z, v.w));
#pragma unroll
    for (int o = 16; o > 0; o >>= 1)
        m = fmaxf(m, __shfl_xor_sync(0xffffffffu, m, o));

    __shared__ float red[8];
    if (lane == 0) red[warp] = m;
    __syncthreads();
    float M = red[0];
#pragma unroll
    for (int i = 1; i < 8; i++) M = fmaxf(M, red[i]);

    v.x = expf(v.x - M);
    v.y = expf(v.y - M);
    v.z = expf(v.z - M);
    v.w = expf(v.w - M);
    float s = v.x + v.y + v.z + v.w;
#pragma unroll
    for (int o = 16; o > 0; o >>= 1)
        s += __shfl_xor_sync(0xffffffffu, s, o);

    __syncthreads();  // red reuse
    if (lane == 0) red[warp] = s;
    __syncthreads();
    float S = red[0];
#pragma unroll
    for (int i = 1; i < 8; i++) S += red[i];

    const float r = 1.0f / S;
    v.x *= r; v.y *= r; v.z *= r; v.w *= r;
    p[t] = v;
}

// ---------------------------------------------------------------------------
// kernel_launch
// ---------------------------------------------------------------------------
extern "C" void kernel_launch(void* const* d_in, const int* in_sizes, int n_in,
                              void* d_out, int out_size)
{
    const float* x      = (const float*)d_in[0];
    const float* w_qkv  = (const float*)d_in[1];
    const float* w_proj = (const float*)d_in[2];
    const float* b_proj = (const float*)d_in[3];
    float* out = (float*)d_out;

    float *qkv, *ctx, *attn_scratch;
    cudaGetSymbolAddress((void**)&qkv, g_qkv);
    cudaGetSymbolAddress((void**)&ctx, g_ctx);
    cudaGetSymbolAddress((void**)&attn_scratch, g_attn);

    const long OUT_ELEMS  = (long)B_DIM * N_DIM * C_DIM;                 // 8388608
    const long ATTN_ELEMS = (long)B_DIM * H_DIM * N_DIM * N_DIM;        // 134217728
    // Reference returns (out, attn): if the harness buffer holds both, write
    // attn straight into it; otherwise keep it in scratch (still needed for ctx).
    float* attn = ((long)out_size >= OUT_ELEMS + ATTN_ELEMS) ? (out + OUT_ELEMS)
                                                             : attn_scratch;

    // 1) qkv = x @ w_qkv                  [8192,3072] = [8192,1024] @ [1024,3072]
    {
        dim3 grid(3 * C_DIM / 128, (B_DIM * N_DIM) / 128, 1);
        sgemm_k<128, 128, 16, 8, 8, false><<<grid, 256>>>(
            x, w_qkv, qkv, nullptr,
            C_DIM, C_DIM, 3 * C_DIM, 3 * C_DIM,
            0, 0, 0, 0, 0, 0, 1, 1.0f);
    }

    // 2) scores = scale * Q @ K^T  per (b,h): [1024,1024] = [1024,64] @ [64,1024]
    {
        dim3 grid(N_DIM / 128, N_DIM / 128, B_DIM * H_DIM);
        sgemm_k<128, 128, 16, 8, 8, true><<<grid, 256>>>(
            qkv /*Q*/, qkv + C_DIM /*K*/, attn, nullptr,
            HD, 3 * C_DIM, 3 * C_DIM, N_DIM,
            /*Q:*/ (long)HD, (long)N_DIM * 3 * C_DIM,
            /*K:*/ (long)HD, (long)N_DIM * 3 * C_DIM,
            /*S:*/ (long)N_DIM * N_DIM, (long)H_DIM * N_DIM * N_DIM,
            H_DIM, 0.125f /* hd^-0.5 */);
    }

    // 3) softmax over keys (rows of 1024)
    softmax1024<<<B_DIM * H_DIM * N_DIM, 256>>>(attn);

    // 4) ctx = attn @ V  per (b,h): [1024,64] = [1024,1024] @ [1024,64]
    {
        dim3 grid(HD / 64, N_DIM / 128, B_DIM * H_DIM);
        sgemm_k<128, 64, 16, 8, 4, false><<<grid, 256>>>(
            attn, qkv + 2 * C_DIM /*V*/, ctx, nullptr,
            N_DIM, N_DIM, 3 * C_DIM, C_DIM,
            /*A:*/ (long)N_DIM * N_DIM, (long)H_DIM * N_DIM * N_DIM,
            /*V:*/ (long)HD, (long)N_DIM * 3 * C_DIM,
            /*C:*/ (long)HD, (long)N_DIM * C_DIM,
            H_DIM, 1.0f);
    }

    // 5) out = ctx @ w_proj + b_proj      [8192,1024] = [8192,1024] @ [1024,1024]
    {
        dim3 grid(C_DIM / 128, (B_DIM * N_DIM) / 128, 1);
        sgemm_k<128, 128, 16, 8, 8, false><<<grid, 256>>>(
            ctx, w_proj, out, b_proj,
            C_DIM, C_DIM, C_DIM, C_DIM,
            0, 0, 0, 0, 0, 0, 1, 1.0f);
    }
}

// round 7
// speedup vs baseline: 1.0000x; 1.0000x over previous
#include <cuda_runtime.h>
#include <cuda_bf16.h>

// Problem constants
#define B_DIM 8
#define N_DIM 1024
#define C_DIM 1024
#define H_DIM 16
#define HD    64

// Scratch (static __device__ arrays: allocation-free per harness rules)
__device__ float g_qkv[(size_t)B_DIM * N_DIM * 3 * C_DIM];        // 96 MiB
__device__ float g_ctx[(size_t)B_DIM * N_DIM * C_DIM];            // 32 MiB
__device__ float g_attn[(size_t)B_DIM * H_DIM * N_DIM * N_DIM];   // 512 MiB (fallback if attn not in d_out)

// ---------------------------------------------------------------------------
// Generic tiled SGEMM: C = alpha * A @ op(B) (+ bias), batched via blockIdx.z
// A row-major [M,K] (lda), B row-major; TRANSB=false: B is [K,N] (ldb),
// TRANSB=true: B is [N,K] (ldb) and we compute A @ B^T.
// Batch offset = (z / innerCount) * s?o + (z % innerCount) * s?i.
// All dims assumed multiples of tile sizes (true for this problem).
// ---------------------------------------------------------------------------
template <int BM, int BN, int BK, int TM, int TN, bool TRANSB>
__global__ void __launch_bounds__((BM / TM) * (BN / TN))
sgemm_k(const float* __restrict__ A, const float* __restrict__ B,
        float* __restrict__ C, const float* __restrict__ bias,
        int K, int lda, int ldb, int ldc,
        long sAi, long sAo, long sBi, long sBo, long sCi, long sCo,
        int innerCount, float alpha)
{
    constexpr int THREADS = (BM / TM) * (BN / TN);
    __shared__ float As[BK][BM];
    __shared__ float Bs[BK][BN];

    const int z  = blockIdx.z;
    const int zo = z / innerCount;
    const int zi = z % innerCount;
    A += (long)zo * sAo + (long)zi * sAi;
    B += (long)zo * sBo + (long)zi * sBi;
    C += (long)zo * sCo + (long)zi * sCi;

    const int m0  = blockIdx.y * BM;
    const int n0  = blockIdx.x * BN;
    const int tid = threadIdx.x;
    const int tx  = tid % (BN / TN);
    const int ty  = tid / (BN / TN);

    float acc[TM][TN];
#pragma unroll
    for (int i = 0; i < TM; i++)
#pragma unroll
        for (int j = 0; j < TN; j++) acc[i][j] = 0.0f;

    for (int k0 = 0; k0 < K; k0 += BK) {
        // ---- load A tile [BM x BK] as float4 along K, store transposed ----
        constexpr int A_F4 = BM * BK / 4;
#pragma unroll
        for (int it = 0; it < A_F4 / THREADS; it++) {
            int i   = tid + it * THREADS;
            int row = i / (BK / 4);
            int c4  = i % (BK / 4);
            float4 v = *reinterpret_cast<const float4*>(
                &A[(long)(m0 + row) * lda + k0 + c4 * 4]);
            As[c4 * 4 + 0][row] = v.x;
            As[c4 * 4 + 1][row] = v.y;
            As[c4 * 4 + 2][row] = v.z;
            As[c4 * 4 + 3][row] = v.w;
        }
        // ---- load B tile [BK x BN] ----
        constexpr int B_F4 = BK * BN / 4;
        if (!TRANSB) {
#pragma unroll
            for (int it = 0; it < B_F4 / THREADS; it++) {
                int i   = tid + it * THREADS;
                int row = i / (BN / 4);
                int c4  = i % (BN / 4);
                float4 v = *reinterpret_cast<const float4*>(
                    &B[(long)(k0 + row) * ldb + n0 + c4 * 4]);
                *reinterpret_cast<float4*>(&Bs[row][c4 * 4]) = v;
            }
        } else {
#pragma unroll
            for (int it = 0; it < B_F4 / THREADS; it++) {
                int i  = tid + it * THREADS;
                int n  = i / (BK / 4);
                int k4 = i % (BK / 4);
                float4 v = *reinterpret_cast<const float4*>(
                    &B[(long)(n0 + n) * ldb + k0 + k4 * 4]);
                Bs[k4 * 4 + 0][n] = v.x;
                Bs[k4 * 4 + 1][n] = v.y;
                Bs[k4 * 4 + 2][n] = v.z;
                Bs[k4 * 4 + 3][n] = v.w;
            }
        }
        __syncthreads();

        // ---- compute ----
#pragma unroll
        for (int kk = 0; kk < BK; kk++) {
            float ra[TM], rb[TN];
#pragma unroll
            for (int i = 0; i < TM; i += 4) {
                float4 t = *reinterpret_cast<const float4*>(&As[kk][ty * TM + i]);
                ra[i] = t.x; ra[i + 1] = t.y; ra[i + 2] = t.z; ra[i + 3] = t.w;
            }
#pragma unroll
            for (int j = 0; j < TN; j += 4) {
                float4 t = *reinterpret_cast<const float4*>(&Bs[kk][tx * TN + j]);
                rb[j] = t.x; rb[j + 1] = t.y; rb[j + 2] = t.z; rb[j + 3] = t.w;
            }
#pragma unroll
            for (int i = 0; i < TM; i++)
#pragma unroll
                for (int j = 0; j < TN; j++)
                    acc[i][j] = fmaf(ra[i], rb[j], acc[i][j]);
        }
        __syncthreads();
    }

    // ---- epilogue ----
#pragma unroll
    for (int i = 0; i < TM; i++) {
#pragma unroll
        for (int j = 0; j < TN; j += 4) {
            float4 v;
            v.x = alpha * acc[i][j + 0];
            v.y = alpha * acc[i][j + 1];
            v.z = alpha * acc[i][j + 2];
            v.w = alpha * acc[i][j + 3];
            if (bias != nullptr) {
                int nb = n0 + tx * TN + j;
                v.x += bias[nb + 0];
                v.y += bias[nb + 1];
                v.z += bias[nb + 2];
                v.w += bias[nb + 3];
            }
            *reinterpret_cast<float4*>(
                &C[(long)(m0 + ty * TM + i) * ldc + n0 + tx * TN + j]) = v;
        }
    }
}

// ---------------------------------------------------------------------------
// Row softmax over rows of exactly 1024 floats. One 256-thread block per row;
// each thread owns one float4 in registers (single read, single write).
// ---------------------------------------------------------------------------
__global__ void softmax1024(float* __restrict__ data)
{
    const long row = blockIdx.x;
    float4* p = reinterpret_cast<float4*>(data + row * 1024);
    const int t    = threadIdx.x;
    const int warp = t >> 5;
    const int lane = t & 31;

    float4 v = p[t];
    float m = fmaxf(fmaxf(v.x, v.y), fmaxf(v.z, v.w));
#pragma unroll
    for (int o = 16; o > 0; o >>= 1)
        m = fmaxf(m, __shfl_xor_sync(0xffffffffu, m, o));

    __shared__ float red[8];
    if (lane == 0) red[warp] = m;
    __syncthreads();
    float M = red[0];
#pragma unroll
    for (int i = 1; i < 8; i++) M = fmaxf(M, red[i]);

    v.x = expf(v.x - M);
    v.y = expf(v.y - M);
    v.z = expf(v.z - M);
    v.w = expf(v.w - M);
    float s = v.x + v.y + v.z + v.w;
#pragma unroll
    for (int o = 16; o > 0; o >>= 1)
        s += __shfl_xor_sync(0xffffffffu, s, o);

    __syncthreads();  // red reuse
    if (lane == 0) red[warp] = s;
    __syncthreads();
    float S = red[0];
#pragma unroll
    for (int i = 1; i < 8; i++) S += red[i];

    const float r = 1.0f / S;
    v.x *= r; v.y *= r; v.z *= r; v.w *= r;
    p[t] = v;
}

// ---------------------------------------------------------------------------
// kernel_launch
// ---------------------------------------------------------------------------
extern "C" void kernel_launch(void* const* d_in, const int* in_sizes, int n_in,
                              void* d_out, int out_size)
{
    const float* x      = (const float*)d_in[0];
    const float* w_qkv  = (const float*)d_in[1];
    const float* w_proj = (const float*)d_in[2];
    const float* b_proj = (const float*)d_in[3];
    float* out = (float*)d_out;

    float *qkv, *ctx, *attn_scratch;
    cudaGetSymbolAddress((void**)&qkv, g_qkv);
    cudaGetSymbolAddress((void**)&ctx, g_ctx);
    cudaGetSymbolAddress((void**)&attn_scratch, g_attn);

    const long OUT_ELEMS  = (long)B_DIM * N_DIM * C_DIM;                 // 8388608
    const long ATTN_ELEMS = (long)B_DIM * H_DIM * N_DIM * N_DIM;        // 134217728
    // Reference returns (out, attn): if the harness buffer holds both, write
    // attn straight into it; otherwise keep it in scratch (still needed for ctx).
    float* attn = ((long)out_size >= OUT_ELEMS + ATTN_ELEMS) ? (out + OUT_ELEMS)
                                                             : attn_scratch;

    // 1) qkv = x @ w_qkv                  [8192,3072] = [8192,1024] @ [1024,3072]
    {
        dim3 grid(3 * C_DIM / 128, (B_DIM * N_DIM) / 128, 1);
        sgemm_k<128, 128, 16, 8, 8, false><<<grid, 256>>>(
            x, w_qkv, qkv, nullptr,
            C_DIM, C_DIM, 3 * C_DIM, 3 * C_DIM,
            0, 0, 0, 0, 0, 0, 1, 1.0f);
    }

    // 2) scores = scale * Q @ K^T  per (b,h): [1024,1024] = [1024,64] @ [64,1024]
    {
        dim3 grid(N_DIM / 128, N_DIM / 128, B_DIM * H_DIM);
        sgemm_k<128, 128, 16, 8, 8, true><<<grid, 256>>>(
            qkv /*Q*/, qkv + C_DIM /*K*/, attn, nullptr,
            HD, 3 * C_DIM, 3 * C_DIM, N_DIM,
            /*Q:*/ (long)HD, (long)N_DIM * 3 * C_DIM,
            /*K:*/ (long)HD, (long)N_DIM * 3 * C_DIM,
            /*S:*/ (long)N_DIM * N_DIM, (long)H_DIM * N_DIM * N_DIM,
            H_DIM, 0.125f /* hd^-0.5 */);
    }

    // 3) softmax over keys (rows of 1024)
    softmax1024<<<B_DIM * H_DIM * N_DIM, 256>>>(attn);

    // 4) ctx = attn @ V  per (b,h): [1024,64] = [1024,1024] @ [1024,64]
    {
        dim3 grid(HD / 64, N_DIM / 128, B_DIM * H_DIM);
        sgemm_k<128, 64, 16, 8, 4, false><<<grid, 256>>>(
            attn, qkv + 2 * C_DIM /*V*/, ctx, nullptr,
            N_DIM, N_DIM, 3 * C_DIM, C_DIM,
            /*A:*/ (long)N_DIM * N_DIM, (long)H_DIM * N_DIM * N_DIM,
            /*V:*/ (long)HD, (long)N_DIM * 3 * C_DIM,
            /*C:*/ (long)HD, (long)N_DIM * C_DIM,
            H_DIM, 1.0f);
    }

    // 5) out = ctx @ w_proj + b_proj      [8192,1024] = [8192,1024] @ [1024,1024]
    {
        dim3 grid(C_DIM / 128, (B_DIM * N_DIM) / 128, 1);
        sgemm_k<128, 128, 16, 8, 8, false><<<grid, 256>>>(
            ctx, w_proj, out, b_proj,
            C_DIM, C_DIM, C_DIM, C_DIM,
            0, 0, 0, 0, 0, 0, 1, 1.0f);
    }
}